// round 4
// baseline (speedup 1.0000x reference)
#include <cuda_runtime.h>
#include <cuda_bf16.h>
#include <math.h>

#define N_NODES 2048
#define DIM     2048
#define HEADS   4
#define RANK    32
#define BATCH   4
#define SEQ     2048
#define LORA_SC 2.0f

// ---------------- scratch (device globals; no allocation allowed) ------------
__device__ float g_wsrc[HEADS * DIM];     // w_src[h,k]
__device__ float g_adst[HEADS];           // a_dst at node N-1
__device__ float g_asrc[N_NODES * HEADS]; // a_src[j,h]
__device__ float g_attn[N_NODES * HEADS]; // attn[j,h] (row i = N-1)
__device__ float g_c[HEADS * DIM];        // c[h,k] = sum_j attn[j,h] node[j,k]
__device__ float g_preln[DIM];            // out[N-1,:] before LN
__device__ float g_mem[DIM];              // layernormed memory
__device__ float g_t[RANK];               // mem @ lora_a.T
__device__ float g_offset[DIM];           // final offset vector

// ---------------- K0: zero the atomic accumulators ---------------------------
__global__ void k_init() {
    int i = blockIdx.x * blockDim.x + threadIdx.x;
    if (i < HEADS * DIM) g_wsrc[i] = 0.f;
    if (i < HEADS * DIM) g_c[i] = 0.f;
    if (i < HEADS) g_adst[i] = 0.f;
}

// ---------------- K1: w_src[h,k] and a_dst[h] in one pass over gat_w ---------
// grid = H * 8(ktile) * 16(dchunk) = 512 blocks, 256 threads.
// w_src[h,k] = sum_d gat_w[h*D+d, k] * att_src[h,d]
// a_dst[h]   = sum_k node[N-1,k] * sum_d gat_w[h*D+d, k] * att_dst[h,d]
__global__ void k_wsrc(const float* __restrict__ gat_w,
                       const float* __restrict__ att_src,
                       const float* __restrict__ att_dst,
                       const float* __restrict__ node) {
    int b = blockIdx.x;
    int dc = b & 15; b >>= 4;
    int kt = b & 7;  b >>= 3;
    int h  = b;
    int k  = kt * 256 + threadIdx.x;
    int d0 = dc * 128;

    __shared__ float s_src[128];
    __shared__ float s_dst[128];
    if (threadIdx.x < 128) {
        s_src[threadIdx.x] = att_src[h * DIM + d0 + threadIdx.x];
        s_dst[threadIdx.x] = att_dst[h * DIM + d0 + threadIdx.x];
    }
    __syncthreads();

    const float* gw = gat_w + (size_t)(h * DIM + d0) * DIM + k;
    float as = 0.f, ad = 0.f;
#pragma unroll 4
    for (int d = 0; d < 128; d++) {
        float w = gw[(size_t)d * DIM];
        as += w * s_src[d];
        ad += w * s_dst[d];
    }
    atomicAdd(&g_wsrc[h * DIM + k], as);

    // a_dst contribution: ad * node_last[k], reduced over the block
    float v = ad * node[(size_t)(N_NODES - 1) * DIM + k];
#pragma unroll
    for (int o = 16; o > 0; o >>= 1) v += __shfl_down_sync(0xffffffffu, v, o);
    __shared__ float s_red[8];
    int lane = threadIdx.x & 31, wid = threadIdx.x >> 5;
    if (lane == 0) s_red[wid] = v;
    __syncthreads();
    if (threadIdx.x == 0) {
        float t = 0.f;
#pragma unroll
        for (int w = 0; w < 8; w++) t += s_red[w];
        atomicAdd(&g_adst[h], t);
    }
}

// ---------------- K2: a_src[j,h] = node[j,:] @ w_src[h,:] --------------------
// grid = N_NODES blocks, 256 threads. w_src staged in smem (32 KB).
__global__ void k_asrc(const float* __restrict__ node) {
    __shared__ float sw[HEADS * DIM];
    for (int i = threadIdx.x; i < HEADS * DIM; i += 256) sw[i] = g_wsrc[i];
    __syncthreads();

    int j = blockIdx.x;
    const float* nd = node + (size_t)j * DIM;
    float a0 = 0.f, a1 = 0.f, a2 = 0.f, a3 = 0.f;
    for (int k = threadIdx.x; k < DIM; k += 256) {
        float x = nd[k];
        a0 += x * sw[k];
        a1 += x * sw[DIM + k];
        a2 += x * sw[2 * DIM + k];
        a3 += x * sw[3 * DIM + k];
    }
#pragma unroll
    for (int o = 16; o > 0; o >>= 1) {
        a0 += __shfl_down_sync(0xffffffffu, a0, o);
        a1 += __shfl_down_sync(0xffffffffu, a1, o);
        a2 += __shfl_down_sync(0xffffffffu, a2, o);
        a3 += __shfl_down_sync(0xffffffffu, a3, o);
    }
    __shared__ float sr[4][8];
    int lane = threadIdx.x & 31, wid = threadIdx.x >> 5;
    if (lane == 0) { sr[0][wid] = a0; sr[1][wid] = a1; sr[2][wid] = a2; sr[3][wid] = a3; }
    __syncthreads();
    if (threadIdx.x < 4) {
        float t = 0.f;
#pragma unroll
        for (int w = 0; w < 8; w++) t += sr[threadIdx.x][w];
        g_asrc[j * HEADS + threadIdx.x] = t;
    }
}

// ---------------- K3: softmax over sources j for target i = N-1 --------------
// grid = HEADS blocks, 1024 threads (2 elements each).
__global__ void k_softmax() {
    int h = blockIdx.x;
    int t = threadIdx.x;
    float adst = g_adst[h];

    float l0 = adst + g_asrc[t * HEADS + h];
    float l1 = adst + g_asrc[(t + 1024) * HEADS + h];
    l0 = (l0 > 0.f) ? l0 : 0.2f * l0;   // leaky_relu 0.2
    l1 = (l1 > 0.f) ? l1 : 0.2f * l1;

    __shared__ float sred[32];
    __shared__ float sbc;
    int lane = t & 31, wid = t >> 5;

    // block max
    float m = fmaxf(l0, l1);
#pragma unroll
    for (int o = 16; o > 0; o >>= 1) m = fmaxf(m, __shfl_down_sync(0xffffffffu, m, o));
    if (lane == 0) sred[wid] = m;
    __syncthreads();
    if (t == 0) {
        float mm = sred[0];
#pragma unroll
        for (int w = 1; w < 32; w++) mm = fmaxf(mm, sred[w]);
        sbc = mm;
    }
    __syncthreads();
    float M = sbc;
    __syncthreads();

    float e0 = __expf(l0 - M), e1 = __expf(l1 - M);
    float s = e0 + e1;
#pragma unroll
    for (int o = 16; o > 0; o >>= 1) s += __shfl_down_sync(0xffffffffu, s, o);
    if (lane == 0) sred[wid] = s;
    __syncthreads();
    if (t == 0) {
        float ss = 0.f;
#pragma unroll
        for (int w = 0; w < 32; w++) ss += sred[w];
        sbc = ss;
    }
    __syncthreads();
    float inv = 1.f / sbc;

    g_attn[t * HEADS + h] = e0 * inv;
    g_attn[(t + 1024) * HEADS + h] = e1 * inv;
}

// ---------------- K4: c[h,k] = sum_j attn[j,h] * node[j,k] -------------------
// grid = 8(ktile) * 32(jchunk) = 256 blocks, 256 threads.
__global__ void k_c(const float* __restrict__ node) {
    int b = blockIdx.x;
    int jc = b & 31;
    int kt = b >> 5;
    int k  = kt * 256 + threadIdx.x;

    __shared__ float sa[64 * HEADS];   // 64 rows of attn
    sa[threadIdx.x] = g_attn[jc * 64 * HEADS + threadIdx.x];
    __syncthreads();

    float c0 = 0.f, c1 = 0.f, c2 = 0.f, c3 = 0.f;
#pragma unroll 4
    for (int jj = 0; jj < 64; jj++) {
        float x = node[(size_t)(jc * 64 + jj) * DIM + k];
        c0 += x * sa[jj * HEADS + 0];
        c1 += x * sa[jj * HEADS + 1];
        c2 += x * sa[jj * HEADS + 2];
        c3 += x * sa[jj * HEADS + 3];
    }
    atomicAdd(&g_c[0 * DIM + k], c0);
    atomicAdd(&g_c[1 * DIM + k], c1);
    atomicAdd(&g_c[2 * DIM + k], c2);
    atomicAdd(&g_c[3 * DIM + k], c3);
}

// ---------------- K5: out[N-1,d] = (1/H) sum_h gat_w[h*D+d,:]·c[h,:] + bias --
// grid = DIM blocks, 256 threads; each block handles all 4 head-rows for one d.
__global__ void k_out(const float* __restrict__ gat_w,
                      const float* __restrict__ gat_bias) {
    int d = blockIdx.x;
    float acc = 0.f;
#pragma unroll
    for (int h = 0; h < HEADS; h++) {
        const float* gw = gat_w + (size_t)(h * DIM + d) * DIM;
        const float* c  = g_c + h * DIM;
        for (int k = threadIdx.x; k < DIM; k += 256)
            acc += gw[k] * c[k];
    }
#pragma unroll
    for (int o = 16; o > 0; o >>= 1) acc += __shfl_down_sync(0xffffffffu, acc, o);
    __shared__ float sr[8];
    int lane = threadIdx.x & 31, wid = threadIdx.x >> 5;
    if (lane == 0) sr[wid] = acc;
    __syncthreads();
    if (threadIdx.x == 0) {
        float t = 0.f;
#pragma unroll
        for (int w = 0; w < 8; w++) t += sr[w];
        g_preln[d] = t * (1.0f / HEADS) + gat_bias[d];
    }
}

// ---------------- K6: LayerNorm over g_preln -> g_mem ------------------------
// 1 block, 1024 threads (2 elements each).
__global__ void k_ln(const float* __restrict__ gamma,
                     const float* __restrict__ beta) {
    int t = threadIdx.x;
    float v0 = g_preln[t];
    float v1 = g_preln[t + 1024];

    __shared__ float sred[32];
    __shared__ float sbc;
    int lane = t & 31, wid = t >> 5;

    float s = v0 + v1;
#pragma unroll
    for (int o = 16; o > 0; o >>= 1) s += __shfl_down_sync(0xffffffffu, s, o);
    if (lane == 0) sred[wid] = s;
    __syncthreads();
    if (t == 0) {
        float ss = 0.f;
#pragma unroll
        for (int w = 0; w < 32; w++) ss += sred[w];
        sbc = ss * (1.0f / DIM);
    }
    __syncthreads();
    float mu = sbc;
    __syncthreads();

    float d0 = v0 - mu, d1 = v1 - mu;
    float q = d0 * d0 + d1 * d1;
#pragma unroll
    for (int o = 16; o > 0; o >>= 1) q += __shfl_down_sync(0xffffffffu, q, o);
    if (lane == 0) sred[wid] = q;
    __syncthreads();
    if (t == 0) {
        float ss = 0.f;
#pragma unroll
        for (int w = 0; w < 32; w++) ss += sred[w];
        sbc = ss * (1.0f / DIM);
    }
    __syncthreads();
    float inv = rsqrtf(sbc + 1e-5f);

    g_mem[t]        = d0 * inv * gamma[t]        + beta[t];
    g_mem[t + 1024] = d1 * inv * gamma[t + 1024] + beta[t + 1024];
}

// ---------------- K7a: t[r] = mem @ lora_a[r,:] ------------------------------
__global__ void k_lora_t(const float* __restrict__ lora_a) {
    int r = blockIdx.x;
    float acc = 0.f;
    const float* la = lora_a + (size_t)r * DIM;
    for (int d = threadIdx.x; d < DIM; d += 256) acc += g_mem[d] * la[d];
#pragma unroll
    for (int o = 16; o > 0; o >>= 1) acc += __shfl_down_sync(0xffffffffu, acc, o);
    __shared__ float sr[8];
    int lane = threadIdx.x & 31, wid = threadIdx.x >> 5;
    if (lane == 0) sr[wid] = acc;
    __syncthreads();
    if (threadIdx.x == 0) {
        float t = 0.f;
#pragma unroll
        for (int w = 0; w < 8; w++) t += sr[w];
        g_t[r] = t;
    }
}

// ---------------- K7b: offset[o] = mem@proj_w[o,:] + proj_b + 2*t@lora_b[o,:]
__global__ void k_offset(const float* __restrict__ proj_w,
                         const float* __restrict__ proj_b,
                         const float* __restrict__ lora_b) {
    int o = blockIdx.x;
    const float* pw = proj_w + (size_t)o * DIM;
    float acc = 0.f;
    for (int d = threadIdx.x; d < DIM; d += 256) acc += g_mem[d] * pw[d];
#pragma unroll
    for (int q = 16; q > 0; q >>= 1) acc += __shfl_down_sync(0xffffffffu, acc, q);
    __shared__ float sr[8];
    int lane = threadIdx.x & 31, wid = threadIdx.x >> 5;
    if (lane == 0) sr[wid] = acc;
    __syncthreads();
    if (threadIdx.x == 0) {
        float t = 0.f;
#pragma unroll
        for (int w = 0; w < 8; w++) t += sr[w];
        float lb = 0.f;
#pragma unroll
        for (int r = 0; r < RANK; r++) lb += g_t[r] * lora_b[o * RANK + r];
        g_offset[o] = t + proj_b[o] + LORA_SC * lb;
    }
}

// ---------------- K8: embedding gather + offset on first tokens --------------
// grid = B*S blocks, 512 threads (one float4 each -> full 2048-float row).
__global__ void k_embed(const int* __restrict__ ids,
                        const float* __restrict__ embed,
                        float* __restrict__ out) {
    int row = blockIdx.x;
    int id = ids[row];
    const float4* src = (const float4*)(embed + (size_t)id * DIM);
    float4 v = src[threadIdx.x];
    if ((row & (SEQ - 1)) == 0) {
        float4 o = ((const float4*)g_offset)[threadIdx.x];
        v.x += o.x; v.y += o.y; v.z += o.z; v.w += o.w;
    }
    ((float4*)out)[(size_t)row * (DIM / 4) + threadIdx.x] = v;
}

// ---------------- launch ------------------------------------------------------
extern "C" void kernel_launch(void* const* d_in, const int* in_sizes, int n_in,
                              void* d_out, int out_size) {
    const float* node     = (const float*)d_in[0];
    const int*   ids      = (const int*)  d_in[1];
    const float* gat_w    = (const float*)d_in[2];
    const float* att_src  = (const float*)d_in[3];
    const float* att_dst  = (const float*)d_in[4];
    const float* gat_bias = (const float*)d_in[5];
    const float* gamma    = (const float*)d_in[6];
    const float* beta     = (const float*)d_in[7];
    const float* proj_w   = (const float*)d_in[8];
    const float* proj_b   = (const float*)d_in[9];
    const float* lora_a   = (const float*)d_in[10];
    const float* lora_b   = (const float*)d_in[11];
    const float* embed    = (const float*)d_in[12];
    float* out = (float*)d_out;

    k_init<<<(HEADS * DIM + 1023) / 1024, 1024>>>();
    k_wsrc<<<HEADS * 8 * 16, 256>>>(gat_w, att_src, att_dst, node);
    k_asrc<<<N_NODES, 256>>>(node);
    k_softmax<<<HEADS, 1024>>>();
    k_c<<<8 * 32, 256>>>(node);
    k_out<<<DIM, 256>>>(gat_w, gat_bias);
    k_ln<<<1, 1024>>>(gamma, beta);
    k_lora_t<<<RANK, 256>>>(lora_a);
    k_offset<<<DIM, 256>>>(proj_w, proj_b, lora_b);
    k_embed<<<BATCH * SEQ, DIM / 4>>>(ids, embed, out);
}

// round 5
// speedup vs baseline: 1.1997x; 1.1997x over previous
#include <cuda_runtime.h>
#include <cuda_bf16.h>
#include <math.h>

#define N_NODES 2048
#define DIM     2048
#define HEADS   4
#define RANK    32
#define BATCH   4
#define SEQ     2048
#define LORA_SC 2.0f

// ---------------- scratch (device globals) -----------------------------------
__device__ float g_wsrc[HEADS * DIM];     // w_src[h,k]
__device__ float g_adst[HEADS];           // a_dst at node N-1
__device__ float g_attn[N_NODES * HEADS]; // UNNORMALIZED exp weights e[j,h]
__device__ float g_z[HEADS];              // Z_h = sum_j e[j,h]
__device__ float g_c[HEADS * DIM];        // c[h,k] = sum_j e[j,h] node[j,k]
__device__ float g_preln[DIM];
__device__ float g_mem[DIM];
__device__ float g_t[RANK];
__device__ float g_offset[DIM];

__device__ __forceinline__ float dot4(float4 a, float4 b) {
    return a.x * b.x + a.y * b.y + a.z * b.z + a.w * b.w;
}

// ---------------- K0: zero accumulators --------------------------------------
__global__ void k_init() {
    int i = blockIdx.x * blockDim.x + threadIdx.x;
    if (i < HEADS * DIM) { g_wsrc[i] = 0.f; g_c[i] = 0.f; }
    if (i < HEADS) { g_adst[i] = 0.f; g_z[i] = 0.f; }
}

// ---------------- K1: w_src[h,k] and a_dst[h], one pass over gat_w -----------
// grid = H(4) x kt(2) x dc(32) = 256 blocks, 256 threads, float4 loads.
// thread owns k-range [kt*1024 + tid*4, +4); d-range dc*64..+64.
__global__ void k_wsrc(const float* __restrict__ gat_w,
                       const float* __restrict__ att_src,
                       const float* __restrict__ att_dst,
                       const float* __restrict__ node) {
    int b = blockIdx.x;
    int dc = b & 31;
    int kt = (b >> 5) & 1;
    int h  = b >> 6;
    int d0 = dc * 64;

    __shared__ float s_src[64];
    __shared__ float s_dst[64];
    if (threadIdx.x < 64) {
        s_src[threadIdx.x] = att_src[h * DIM + d0 + threadIdx.x];
        s_dst[threadIdx.x] = att_dst[h * DIM + d0 + threadIdx.x];
    }
    __syncthreads();

    const float4* gw4 = (const float4*)(gat_w + (size_t)(h * DIM + d0) * DIM)
                        + kt * 256 + threadIdx.x;
    float4 as = make_float4(0.f, 0.f, 0.f, 0.f);
    float4 ad = make_float4(0.f, 0.f, 0.f, 0.f);
#pragma unroll 4
    for (int d = 0; d < 64; d++) {
        float4 w = gw4[(size_t)d * (DIM / 4)];
        float ss = s_src[d], sd = s_dst[d];
        as.x += w.x * ss; as.y += w.y * ss; as.z += w.z * ss; as.w += w.w * ss;
        ad.x += w.x * sd; ad.y += w.y * sd; ad.z += w.z * sd; ad.w += w.w * sd;
    }
    int k = kt * 1024 + threadIdx.x * 4;
    atomicAdd(&g_wsrc[h * DIM + k + 0], as.x);
    atomicAdd(&g_wsrc[h * DIM + k + 1], as.y);
    atomicAdd(&g_wsrc[h * DIM + k + 2], as.z);
    atomicAdd(&g_wsrc[h * DIM + k + 3], as.w);

    // a_dst: dot with last node's features
    const float4* nl4 = (const float4*)(node + (size_t)(N_NODES - 1) * DIM)
                        + kt * 256 + threadIdx.x;
    float v = dot4(ad, *nl4);
#pragma unroll
    for (int o = 16; o > 0; o >>= 1) v += __shfl_down_sync(0xffffffffu, v, o);
    __shared__ float s_red[8];
    int lane = threadIdx.x & 31, wid = threadIdx.x >> 5;
    if (lane == 0) s_red[wid] = v;
    __syncthreads();
    if (threadIdx.x == 0) {
        float t = 0.f;
#pragma unroll
        for (int w = 0; w < 8; w++) t += s_red[w];
        atomicAdd(&g_adst[h], t);
    }
}

// ---------------- K2: e[j,h] = exp(leaky(adst_h + node[j]·w_src[h])) ---------
// grid = 256 blocks x 256 threads; warp w handles row j0+w (8 rows/block).
__global__ void k_asrc(const float* __restrict__ node) {
    __shared__ float4 sw4[HEADS * DIM / 4];   // 32 KB
    for (int i = threadIdx.x; i < HEADS * DIM / 4; i += 256)
        sw4[i] = ((const float4*)g_wsrc)[i];
    __syncthreads();

    int lane = threadIdx.x & 31;
    int w    = threadIdx.x >> 5;
    int j    = blockIdx.x * 8 + w;

    const float4* nd4 = (const float4*)(node + (size_t)j * DIM);
    float a0 = 0.f, a1 = 0.f, a2 = 0.f, a3 = 0.f;
#pragma unroll
    for (int i = 0; i < 16; i++) {
        int idx = lane + i * 32;
        float4 x = nd4[idx];
        a0 += dot4(x, sw4[idx]);
        a1 += dot4(x, sw4[512 + idx]);
        a2 += dot4(x, sw4[1024 + idx]);
        a3 += dot4(x, sw4[1536 + idx]);
    }
#pragma unroll
    for (int o = 16; o > 0; o >>= 1) {
        a0 += __shfl_down_sync(0xffffffffu, a0, o);
        a1 += __shfl_down_sync(0xffffffffu, a1, o);
        a2 += __shfl_down_sync(0xffffffffu, a2, o);
        a3 += __shfl_down_sync(0xffffffffu, a3, o);
    }
    if (lane == 0) {
        float as[4] = {a0, a1, a2, a3};
#pragma unroll
        for (int h = 0; h < HEADS; h++) {
            float l = g_adst[h] + as[h];
            l = (l > 0.f) ? l : 0.2f * l;          // leaky_relu(0.2)
            g_attn[j * HEADS + h] = __expf(l);     // unnormalized
        }
    }
}

// ---------------- K3: c[h,k] += e[j,h] node[j,k];  Z_h += e[j,h] -------------
// grid = kt(2) x jc(32) = 64 blocks, 256 threads; 64 rows per block; node L2-hot.
__global__ void k_c(const float* __restrict__ node) {
    int jc = blockIdx.x & 31;
    int kt = blockIdx.x >> 5;
    int j0 = jc * 64;

    __shared__ float sa[64 * HEADS];
    sa[threadIdx.x] = g_attn[j0 * HEADS + threadIdx.x];
    __syncthreads();

    if (kt == 0 && threadIdx.x < HEADS) {
        float s = 0.f;
#pragma unroll
        for (int jj = 0; jj < 64; jj++) s += sa[jj * HEADS + threadIdx.x];
        atomicAdd(&g_z[threadIdx.x], s);
    }

    float4 c0 = make_float4(0,0,0,0), c1 = c0, c2 = c0, c3 = c0;
#pragma unroll 2
    for (int jj = 0; jj < 64; jj++) {
        const float4* nd4 = (const float4*)(node + (size_t)(j0 + jj) * DIM)
                            + kt * 256 + threadIdx.x;
        float4 x = *nd4;
        float e0 = sa[jj * HEADS + 0], e1 = sa[jj * HEADS + 1];
        float e2 = sa[jj * HEADS + 2], e3 = sa[jj * HEADS + 3];
        c0.x += x.x*e0; c0.y += x.y*e0; c0.z += x.z*e0; c0.w += x.w*e0;
        c1.x += x.x*e1; c1.y += x.y*e1; c1.z += x.z*e1; c1.w += x.w*e1;
        c2.x += x.x*e2; c2.y += x.y*e2; c2.z += x.z*e2; c2.w += x.w*e2;
        c3.x += x.x*e3; c3.y += x.y*e3; c3.z += x.z*e3; c3.w += x.w*e3;
    }
    int k = kt * 1024 + threadIdx.x * 4;
    float4 cc[4] = {c0, c1, c2, c3};
#pragma unroll
    for (int h = 0; h < HEADS; h++) {
        atomicAdd(&g_c[h * DIM + k + 0], cc[h].x);
        atomicAdd(&g_c[h * DIM + k + 1], cc[h].y);
        atomicAdd(&g_c[h * DIM + k + 2], cc[h].z);
        atomicAdd(&g_c[h * DIM + k + 3], cc[h].w);
    }
}

// ---------------- K4: preln[d] = (1/H) sum_h (1/Z_h) gat_w[hD+d,:]·c[h,:] ----
__global__ void k_out(const float* __restrict__ gat_w,
                      const float* __restrict__ gat_bias) {
    int d = blockIdx.x;
    float total = 0.f;
#pragma unroll
    for (int h = 0; h < HEADS; h++) {
        const float4* gw4 = (const float4*)(gat_w + (size_t)(h * DIM + d) * DIM);
        const float4* c4  = (const float4*)(g_c + h * DIM);
        float acc = 0.f;
#pragma unroll
        for (int i = 0; i < 2; i++) {
            int idx = threadIdx.x + i * 256;
            acc += dot4(gw4[idx], c4[idx]);
        }
        total += acc * (1.0f / g_z[h]);
    }
#pragma unroll
    for (int o = 16; o > 0; o >>= 1) total += __shfl_down_sync(0xffffffffu, total, o);
    __shared__ float sr[8];
    int lane = threadIdx.x & 31, wid = threadIdx.x >> 5;
    if (lane == 0) sr[wid] = total;
    __syncthreads();
    if (threadIdx.x == 0) {
        float t = 0.f;
#pragma unroll
        for (int w = 0; w < 8; w++) t += sr[w];
        g_preln[d] = t * (1.0f / HEADS) + gat_bias[d];
    }
}

// ---------------- K5: LayerNorm + LoRA-A  (1 block, 1024 threads) ------------
__global__ void k_ln_lora(const float* __restrict__ gamma,
                          const float* __restrict__ beta,
                          const float* __restrict__ lora_a) {
    __shared__ float s_mem[DIM];
    __shared__ float sred[32];
    __shared__ float sbc;
    int t = threadIdx.x;
    int lane = t & 31, wid = t >> 5;

    float v0 = g_preln[t];
    float v1 = g_preln[t + 1024];

    float s = v0 + v1;
#pragma unroll
    for (int o = 16; o > 0; o >>= 1) s += __shfl_down_sync(0xffffffffu, s, o);
    if (lane == 0) sred[wid] = s;
    __syncthreads();
    if (t == 0) {
        float ss = 0.f;
#pragma unroll
        for (int w = 0; w < 32; w++) ss += sred[w];
        sbc = ss * (1.0f / DIM);
    }
    __syncthreads();
    float mu = sbc;
    __syncthreads();

    float d0 = v0 - mu, d1 = v1 - mu;
    float q = d0 * d0 + d1 * d1;
#pragma unroll
    for (int o = 16; o > 0; o >>= 1) q += __shfl_down_sync(0xffffffffu, q, o);
    if (lane == 0) sred[wid] = q;
    __syncthreads();
    if (t == 0) {
        float ss = 0.f;
#pragma unroll
        for (int w = 0; w < 32; w++) ss += sred[w];
        sbc = ss * (1.0f / DIM);
    }
    __syncthreads();
    float inv = rsqrtf(sbc + 1e-5f);

    float m0 = d0 * inv * gamma[t]        + beta[t];
    float m1 = d1 * inv * gamma[t + 1024] + beta[t + 1024];
    g_mem[t] = m0;          s_mem[t] = m0;
    g_mem[t + 1024] = m1;   s_mem[t + 1024] = m1;
    __syncthreads();

    // LoRA-A: warp r computes t[r] = mem · lora_a[r,:]
    const float4* la4 = (const float4*)(lora_a + (size_t)wid * DIM);
    const float4* sm4 = (const float4*)s_mem;
    float acc = 0.f;
#pragma unroll
    for (int i = 0; i < 16; i++) {
        int idx = lane + i * 32;
        acc += dot4(la4[idx], sm4[idx]);
    }
#pragma unroll
    for (int o = 16; o > 0; o >>= 1) acc += __shfl_down_sync(0xffffffffu, acc, o);
    if (lane == 0) g_t[wid] = acc;
}

// ---------------- K6: offset[o] = mem·proj_w[o,:] + b + 2·(t·lora_b[o,:]) ----
__global__ void k_offset(const float* __restrict__ proj_w,
                         const float* __restrict__ proj_b,
                         const float* __restrict__ lora_b) {
    int o = blockIdx.x;
    const float4* pw4 = (const float4*)(proj_w + (size_t)o * DIM);
    const float4* sm4 = (const float4*)g_mem;
    float acc = 0.f;
#pragma unroll
    for (int i = 0; i < 2; i++) {
        int idx = threadIdx.x + i * 256;
        acc += dot4(pw4[idx], sm4[idx]);
    }
#pragma unroll
    for (int q = 16; q > 0; q >>= 1) acc += __shfl_down_sync(0xffffffffu, acc, q);
    __shared__ float sr[8];
    __shared__ float s_total;
    int lane = threadIdx.x & 31, wid = threadIdx.x >> 5;
    if (lane == 0) sr[wid] = acc;
    __syncthreads();
    if (threadIdx.x == 0) {
        float t = 0.f;
#pragma unroll
        for (int w = 0; w < 8; w++) t += sr[w];
        s_total = t;
    }
    __syncthreads();
    if (wid == 0) {   // warp 0: lora term, lane r
        float v = g_t[lane] * lora_b[o * RANK + lane];
#pragma unroll
        for (int q = 16; q > 0; q >>= 1) v += __shfl_down_sync(0xffffffffu, v, q);
        if (lane == 0)
            g_offset[o] = s_total + proj_b[o] + LORA_SC * v;
    }
}

// ---------------- K7a: embedding gather for all non-first tokens -------------
__global__ void k_embed_body(const int* __restrict__ ids,
                             const float* __restrict__ embed,
                             float* __restrict__ out) {
    int row = blockIdx.x;
    if ((row & (SEQ - 1)) == 0) return;   // first tokens handled separately
    int id = ids[row];
    const float4* src = (const float4*)(embed + (size_t)id * DIM);
    ((float4*)out)[(size_t)row * (DIM / 4) + threadIdx.x] = src[threadIdx.x];
}

// ---------------- K7b: first tokens: gather + offset -------------------------
__global__ void k_embed_first(const int* __restrict__ ids,
                              const float* __restrict__ embed,
                              float* __restrict__ out) {
    int row = blockIdx.x * SEQ;
    int id = ids[row];
    const float4* src = (const float4*)(embed + (size_t)id * DIM);
    float4 v = src[threadIdx.x];
    float4 o = ((const float4*)g_offset)[threadIdx.x];
    v.x += o.x; v.y += o.y; v.z += o.z; v.w += o.w;
    ((float4*)out)[(size_t)row * (DIM / 4) + threadIdx.x] = v;
}

// ---------------- launch ------------------------------------------------------
extern "C" void kernel_launch(void* const* d_in, const int* in_sizes, int n_in,
                              void* d_out, int out_size) {
    const float* node     = (const float*)d_in[0];
    const int*   ids      = (const int*)  d_in[1];
    const float* gat_w    = (const float*)d_in[2];
    const float* att_src  = (const float*)d_in[3];
    const float* att_dst  = (const float*)d_in[4];
    const float* gat_bias = (const float*)d_in[5];
    const float* gamma    = (const float*)d_in[6];
    const float* beta     = (const float*)d_in[7];
    const float* proj_w   = (const float*)d_in[8];
    const float* proj_b   = (const float*)d_in[9];
    const float* lora_a   = (const float*)d_in[10];
    const float* lora_b   = (const float*)d_in[11];
    const float* embed    = (const float*)d_in[12];
    float* out = (float*)d_out;

    // Fork: embed body is independent of the GAT chain — run it on a side
    // stream so its ~130 MB of traffic overlaps the chain's latency.
    cudaStream_t s2;
    cudaEvent_t e_fork, e_join;
    cudaStreamCreateWithFlags(&s2, cudaStreamNonBlocking);
    cudaEventCreateWithFlags(&e_fork, cudaEventDisableTiming);
    cudaEventCreateWithFlags(&e_join, cudaEventDisableTiming);

    cudaEventRecord(e_fork, 0);
    cudaStreamWaitEvent(s2, e_fork, 0);
    k_embed_body<<<BATCH * SEQ, DIM / 4, 0, s2>>>(ids, embed, out);
    cudaEventRecord(e_join, s2);

    // Main chain on the capture stream.
    k_init<<<8, 1024>>>();
    k_wsrc<<<256, 256>>>(gat_w, att_src, att_dst, node);
    k_asrc<<<N_NODES / 8, 256>>>(node);
    k_c<<<64, 256>>>(node);
    k_out<<<DIM, 256>>>(gat_w, gat_bias);
    k_ln_lora<<<1, 1024>>>(gamma, beta, lora_a);
    k_offset<<<DIM, 256>>>(proj_w, proj_b, lora_b);
    k_embed_first<<<BATCH, DIM / 4>>>(ids, embed, out);

    // Join the side stream so the graph's end depends on the body writes.
    cudaStreamWaitEvent(0, e_join, 0);
}